// round 2
// baseline (speedup 1.0000x reference)
#include <cuda_runtime.h>
#include <math.h>

// ---------------- problem constants ----------------
#define BB     16
#define F1N    16
#define CC     64
#define TTOT   1000
#define KK     64
#define C2N    32
#define PWN    16
#define EPSF   1e-5f

// ---------------- kernel-1 tiling ----------------
#define TILE   40          // time points per block
#define NTILE  25          // 25*40 = 1000
#define TSUB   20          // chunk of t processed per phase round
#define NCHUNK 2
#define TGRP   10          // t per thread in conv inner loop
#define XS_W   104         // TILE + 63 halo + 1 pad

// smem float counts
#define NF_XS   (CC*XS_W)       // 6656
#define NF_WS   (F1N*KK)        // 1024
#define NF_AH   (CC*CC)         // 4096
#define NF_DW   (C2N*CC)        // 2048
#define NF_ES   (F1N*CC*TSUB)   // 20480
#define NF_XG   (CC*TSUB)       // 1280
#define NF_AX   (CC*TSUB)       // 1280
#define NF_SMALL (F1N+F1N+C2N+C2N+C2N) // 144
#define SMEM_FLOATS (NF_XS+NF_WS+NF_AH+NF_DW+NF_ES+NF_XG+NF_AX+NF_SMALL)
#define SMEM_BYTES  (SMEM_FLOATS*4)

__device__ float g_h2[BB * C2N * TTOT];   // stage-3 output scratch (2 MB)

__device__ __forceinline__ float eluf(float v) { return v > 0.f ? v : expm1f(v); }

// ============================================================
// Kernel 1: temporal conv + BN1 + ELU + GCN residual +
//           depthwise expansion + BN2  ->  g_h2[b][c2][t]
// grid (NTILE, BB), 512 threads, dynamic smem
// ============================================================
__global__ void __launch_bounds__(512, 1)
k1_front(const float* __restrict__ x,
         const float* __restrict__ ahat_g,
         const float* __restrict__ w1,  const float* __restrict__ b1c,
         const float* __restrict__ g1,  const float* __restrict__ bb1,
         const float* __restrict__ m1,  const float* __restrict__ v1,
         const float* __restrict__ gcw, const float* __restrict__ gcb,
         const float* __restrict__ dww_g, const float* __restrict__ dwb,
         const float* __restrict__ g2,  const float* __restrict__ bb2,
         const float* __restrict__ m2,  const float* __restrict__ v2)
{
    extern __shared__ float sm[];
    float* xs  = sm;                 // [CC][XS_W]
    float* ws  = xs  + NF_XS;        // [F1][KK]  (BN1-scaled conv weights)
    float* ah  = ws  + NF_WS;        // [CC][CC]
    float* dw  = ah  + NF_AH;        // [C2][CC]
    float* es  = dw  + NF_DW;        // [F1][CC][TSUB]
    float* xg  = es  + NF_ES;        // [CC][TSUB]
    float* ax  = xg  + NF_XG;        // [CC][TSUB]
    float* o1s = ax  + NF_AX;        // [F1]
    float* gw  = o1s + F1N;          // [F1]
    float* s2  = gw  + F1N;          // [C2]
    float* sh2 = s2  + C2N;          // [C2]
    float* cst = sh2 + C2N;          // [C2]

    const int tid = threadIdx.x;
    const int b   = blockIdx.y;
    const int t0  = blockIdx.x * TILE;

    // ---- cooperative loads ----
    for (int i = tid; i < NF_XS; i += blockDim.x) {
        int c = i / XS_W, j = i % XS_W;
        int tg = t0 - 31 + j;
        xs[i] = (tg >= 0 && tg < TTOT) ? x[(b * CC + c) * TTOT + tg] : 0.f;
    }
    for (int i = tid; i < NF_WS; i += blockDim.x) {
        int f = i / KK;
        float s1 = g1[f] * rsqrtf(v1[f] + EPSF);
        ws[i] = w1[i] * s1;
    }
    for (int i = tid; i < NF_AH; i += blockDim.x) ah[i] = ahat_g[i];
    for (int i = tid; i < NF_DW; i += blockDim.x) dw[i] = dww_g[i];
    if (tid < F1N) {
        float s1 = g1[tid] * rsqrtf(v1[tid] + EPSF);
        o1s[tid] = b1c[tid] * s1 + bb1[tid] - m1[tid] * s1;
        gw[tid]  = gcw[tid];
    }
    if (tid < C2N) {
        float s = g2[tid] * rsqrtf(v2[tid] + EPSF);
        s2[tid]  = s;
        sh2[tid] = bb2[tid] - m2[tid] * s;
    }
    __syncthreads();
    if (tid < C2N) {
        float wsum = 0.f;
        for (int c = 0; c < CC; ++c) wsum += dw[tid * CC + c];
        cst[tid] = gcb[tid >> 1] * wsum + dwb[tid];
    }
    __syncthreads();

    for (int chk = 0; chk < NCHUNK; ++chk) {
        const int ct = chk * TSUB;

        // ---- phase A: conv + BN1 + ELU -> es ----
        for (int it = tid; it < F1N * CC * 2; it += blockDim.x) {
            int f  = it >> 7;          // /128
            int r  = it & 127;
            int c  = r >> 1;
            int tg = r & 1;
            int base = ct + tg * TGRP;
            const float* wrow = ws + f * KK;
            const float* xrow = xs + c * XS_W;
            float acc[TGRP], win[TGRP];
            #pragma unroll
            for (int i = 0; i < TGRP; ++i) { acc[i] = 0.f; win[i] = xrow[base + i]; }
            #pragma unroll
            for (int k = 0; k < KK; ++k) {
                float wv = wrow[k];
                #pragma unroll
                for (int i = 0; i < TGRP; ++i)
                    acc[i] = fmaf(wv, win[(k + i) % TGRP], acc[i]);
                win[k % TGRP] = xrow[base + k + TGRP];
            }
            float o1 = o1s[f];
            float* ed = es + (f * CC + c) * TSUB + tg * TGRP;
            #pragma unroll
            for (int i = 0; i < TGRP; ++i) ed[i] = eluf(acc[i] + o1);
        }
        __syncthreads();

        // ---- phase B: xg = mean_f es ----
        for (int idx = tid; idx < CC * TSUB; idx += blockDim.x) {
            int c = idx / TSUB, tt = idx % TSUB;
            float s = 0.f;
            #pragma unroll
            for (int f = 0; f < F1N; ++f) s += es[(f * CC + c) * TSUB + tt];
            xg[idx] = s * (1.f / F1N);
        }
        __syncthreads();

        // ---- phase C: ax = a_hat @ xg ----
        for (int idx = tid; idx < CC * TSUB; idx += blockDim.x) {
            int c = idx / TSUB, tt = idx % TSUB;
            const float* ar = ah + c * CC;
            float s = 0.f;
            #pragma unroll 8
            for (int j = 0; j < CC; ++j) s = fmaf(ar[j], xg[j * TSUB + tt], s);
            ax[idx] = s;
        }
        __syncthreads();

        // ---- phase D: depthwise expansion + GCN terms + BN2 -> g_h2 ----
        for (int idx = tid; idx < C2N * TSUB; idx += blockDim.x) {
            int c2 = idx / TSUB, tt = idx % TSUB;
            int f = c2 >> 1;
            float gwf = gw[f];
            const float* dr = dw + c2 * CC;
            float s = 0.f;
            #pragma unroll 8
            for (int c = 0; c < CC; ++c)
                s = fmaf(dr[c], es[(f * CC + c) * TSUB + tt] + gwf * ax[c * TSUB + tt], s);
            float outv = (s + cst[c2]) * s2[c2] + sh2[c2];
            g_h2[(b * C2N + c2) * TTOT + t0 + ct + tt] = outv;
        }
        __syncthreads();
    }
}

// ============================================================
// Kernel 2: channel attn + spatial attn + ELU/pool + sep conv +
//           BN3 + ELU/pool -> out [B][C2][3]
// grid (BB), 256 threads
// ============================================================
__global__ void __launch_bounds__(256, 1)
k2_back(const float* __restrict__ caw1, const float* __restrict__ cab1,
        const float* __restrict__ caw2, const float* __restrict__ cab2,
        const float* __restrict__ saw,
        const float* __restrict__ sag, const float* __restrict__ sab,
        const float* __restrict__ sam, const float* __restrict__ sav,
        const float* __restrict__ sepw, const float* __restrict__ sepb,
        const float* __restrict__ g3, const float* __restrict__ bb3,
        const float* __restrict__ m3, const float* __restrict__ v3,
        float* __restrict__ out)
{
    __shared__ float sstat[C2N], att[C2N];
    __shared__ float mm[TTOT], mx[TTOT], sg[TTOT];
    __shared__ float q[C2N * 62];

    const int b   = blockIdx.x;
    const int tid = threadIdx.x;
    const float* h2 = g_h2 + b * C2N * TTOT;

    // ---- channel stats: mean + max over t per c2 ----
    {
        int warp = tid >> 5, lane = tid & 31;
        for (int c2 = warp; c2 < C2N; c2 += 8) {
            float sm_ = 0.f, mx_ = -INFINITY;
            for (int t = lane; t < TTOT; t += 32) {
                float v = h2[c2 * TTOT + t];
                sm_ += v; mx_ = fmaxf(mx_, v);
            }
            #pragma unroll
            for (int o = 16; o > 0; o >>= 1) {
                sm_ += __shfl_down_sync(0xffffffffu, sm_, o);
                mx_  = fmaxf(mx_, __shfl_down_sync(0xffffffffu, mx_, o));
            }
            if (lane == 0) sstat[c2] = sm_ * (1.f / TTOT) + mx_;
        }
    }
    __syncthreads();

    // ---- SE MLP -> att ----
    if (tid < C2N) {
        float r0 = cab1[0], r1 = cab1[1];
        for (int j = 0; j < C2N; ++j) {
            r0 += caw1[j] * sstat[j];
            r1 += caw1[C2N + j] * sstat[j];
        }
        r0 = fmaxf(r0, 0.f); r1 = fmaxf(r1, 0.f);
        float z = cab2[tid] + caw2[tid * 2] * r0 + caw2[tid * 2 + 1] * r1;
        att[tid] = 1.f / (1.f + expf(-z));
    }
    __syncthreads();

    // ---- spatial stats over channels (after att) ----
    for (int t = tid; t < TTOT; t += blockDim.x) {
        float sm_ = 0.f, mx_ = -INFINITY;
        for (int c2 = 0; c2 < C2N; ++c2) {
            float v = h2[c2 * TTOT + t] * att[c2];
            sm_ += v; mx_ = fmaxf(mx_, v);
        }
        mm[t] = sm_ * (1.f / C2N);
        mx[t] = mx_;
    }
    __syncthreads();

    // ---- 1x3 conv (middle row of 3x3) + BN + sigmoid ----
    {
        float ssa = sag[0] * rsqrtf(sav[0] + EPSF);
        float sha = sab[0] - sam[0] * ssa;
        for (int t = tid; t < TTOT; t += blockDim.x) {
            float acc = 0.f;
            #pragma unroll
            for (int kw = 0; kw < 3; ++kw) {
                int tt = t - 1 + kw;
                if (tt >= 0 && tt < TTOT)
                    acc += saw[3 + kw] * mm[tt] + saw[12 + kw] * mx[tt];
            }
            float z = acc * ssa + sha;
            sg[t] = 1.f / (1.f + expf(-z));
        }
    }
    __syncthreads();

    // ---- apply both attns, ELU, avgpool 16 -> q[c2][0..61] ----
    for (int idx = tid; idx < C2N * 62; idx += blockDim.x) {
        int c2 = idx / 62, to = idx % 62;
        float a = att[c2], acc = 0.f;
        #pragma unroll
        for (int j = 0; j < PWN; ++j) {
            int t = to * PWN + j;
            acc += eluf(h2[c2 * TTOT + t] * a * sg[t]);
        }
        q[idx] = acc * (1.f / PWN);
    }
    __syncthreads();

    // ---- depthwise sep conv (SAME pad 7/8) + BN3 + ELU + avgpool 16 ----
    if (tid < C2N * 3) {
        int c2 = tid / 3, to = tid % 3;
        float s3  = g3[c2] * rsqrtf(v3[c2] + EPSF);
        float sh3 = bb3[c2] - m3[c2] * s3;
        float acc = 0.f;
        for (int j = 0; j < PWN; ++j) {
            int t = to * PWN + j;
            float y = sepb[c2];
            #pragma unroll
            for (int u = 0; u < PWN; ++u) {
                int tq = t - 7 + u;
                if (tq >= 0 && tq < 62) y += sepw[c2 * PWN + u] * q[c2 * 62 + tq];
            }
            acc += eluf(y * s3 + sh3);
        }
        out[b * (C2N * 3) + tid] = acc * (1.f / PWN);
    }
}

// ============================================================
extern "C" void kernel_launch(void* const* d_in, const int* in_sizes, int n_in,
                              void* d_out, int out_size)
{
    const float* x     = (const float*)d_in[0];
    const float* ahat  = (const float*)d_in[1];
    const float* w1    = (const float*)d_in[2];
    const float* b1c   = (const float*)d_in[3];
    const float* g1    = (const float*)d_in[4];
    const float* bb1   = (const float*)d_in[5];
    const float* m1    = (const float*)d_in[6];
    const float* v1    = (const float*)d_in[7];
    const float* gcw   = (const float*)d_in[8];
    const float* gcb   = (const float*)d_in[9];
    const float* dww   = (const float*)d_in[10];
    const float* dwb   = (const float*)d_in[11];
    const float* g2    = (const float*)d_in[12];
    const float* bb2   = (const float*)d_in[13];
    const float* m2    = (const float*)d_in[14];
    const float* v2    = (const float*)d_in[15];
    const float* caw1  = (const float*)d_in[16];
    const float* cab1  = (const float*)d_in[17];
    const float* caw2  = (const float*)d_in[18];
    const float* cab2  = (const float*)d_in[19];
    const float* saw   = (const float*)d_in[20];
    const float* sag   = (const float*)d_in[21];
    const float* sab   = (const float*)d_in[22];
    const float* sam   = (const float*)d_in[23];
    const float* sav   = (const float*)d_in[24];
    const float* sepw  = (const float*)d_in[25];
    const float* sepb  = (const float*)d_in[26];
    const float* g3    = (const float*)d_in[27];
    const float* bb3   = (const float*)d_in[28];
    const float* m3    = (const float*)d_in[29];
    const float* v3    = (const float*)d_in[30];

    cudaFuncSetAttribute(k1_front, cudaFuncAttributeMaxDynamicSharedMemorySize,
                         SMEM_BYTES);

    dim3 grid1(NTILE, BB);
    k1_front<<<grid1, 512, SMEM_BYTES>>>(x, ahat, w1, b1c, g1, bb1, m1, v1,
                                         gcw, gcb, dww, dwb, g2, bb2, m2, v2);

    k2_back<<<BB, 256>>>(caw1, cab1, caw2, cab2, saw, sag, sab, sam, sav,
                         sepw, sepb, g3, bb3, m3, v3, (float*)d_out);
}

// round 3
// speedup vs baseline: 1.0712x; 1.0712x over previous
#include <cuda_runtime.h>
#include <math.h>

// ---------------- problem constants ----------------
#define BB     16
#define F1N    16
#define CC     64
#define TTOT   1000
#define KK     64
#define C2N    32
#define PWN    16
#define EPSF   1e-5f

// ---------------- kernel-1 tiling ----------------
#define TILE   40          // time points per block
#define NTILE  25          // 25*40 = 1000
#define TSUB   20          // chunk of t per phase round
#define NCHUNK 2
#define TGRP   10          // t per thread in conv inner loop
#define XS_W   103         // TILE + 63 halo (odd -> conflict-free)
#define ES_S   21          // padded row stride for es

// smem float counts
#define NF_XS   (CC*XS_W)       // 6592
#define NF_WS   (F1N*KK)        // 1024
#define NF_AH   (CC*CC)         // 4096
#define NF_DW   (C2N*CC)        // 2048
#define NF_ES   (F1N*CC*ES_S)   // 21504
#define NF_XG   (CC*TSUB)       // 1280
#define NF_AX   (CC*TSUB)       // 1280
#define NF_SMALL (F1N+F1N+C2N+C2N+C2N) // 144
#define SMEM_FLOATS (NF_XS+NF_WS+NF_AH+NF_DW+NF_ES+NF_XG+NF_AX+NF_SMALL)
#define SMEM_BYTES  (SMEM_FLOATS*4)

// K2 tiling
#define K2B_W    8          // pool windows per k2b tile
#define K2B_T    (K2B_W*PWN)  // 128 t per tile
#define NTILE2   8          // 7 full tiles + 1 partial (6 windows)
#define NPOOL    62         // 992/16

__device__ float g_h2[BB * C2N * TTOT];    // stage-3 output (2 MB)
__device__ float g_stat[BB * C2N * 2];     // per-(b,c2) sum / max
__device__ float g_q[BB * C2N * NPOOL];    // pooled pre-sepconv

__device__ __forceinline__ float eluf(float v) { return v > 0.f ? v : expm1f(v); }
__device__ __forceinline__ float sigmf(float z) { return 1.f / (1.f + expf(-z)); }

// ============================================================
// Kernel 1: temporal conv + BN1 + ELU + GCN residual +
//           depthwise expansion + BN2  ->  g_h2[b][c2][t]
// grid (NTILE, BB), 512 threads
// ============================================================
__global__ void __launch_bounds__(512, 1)
k1_front(const float* __restrict__ x,
         const float* __restrict__ ahat_g,
         const float* __restrict__ w1,  const float* __restrict__ b1c,
         const float* __restrict__ g1,  const float* __restrict__ bb1,
         const float* __restrict__ m1,  const float* __restrict__ v1,
         const float* __restrict__ gcw, const float* __restrict__ gcb,
         const float* __restrict__ dww_g, const float* __restrict__ dwb,
         const float* __restrict__ g2,  const float* __restrict__ bb2,
         const float* __restrict__ m2,  const float* __restrict__ v2)
{
    extern __shared__ float sm[];
    float* xs  = sm;                 // [CC][XS_W]
    float* ws  = xs  + NF_XS;        // [F1][KK]  (BN1-scaled weights)
    float* ah  = ws  + NF_WS;        // [CC][CC]
    float* dw  = ah  + NF_AH;        // [C2][CC]
    float* es  = dw  + NF_DW;        // [F1][CC][ES_S]
    float* xg  = es  + NF_ES;        // [CC][TSUB]
    float* ax  = xg  + NF_XG;        // [CC][TSUB]
    float* o1s = ax  + NF_AX;        // [F1]
    float* gw  = o1s + F1N;          // [F1]
    float* s2  = gw  + F1N;          // [C2]
    float* sh2 = s2  + C2N;          // [C2]
    float* cst = sh2 + C2N;          // [C2]

    const int tid = threadIdx.x;
    const int b   = blockIdx.y;
    const int t0  = blockIdx.x * TILE;

    // ---- cooperative loads ----
    for (int i = tid; i < NF_XS; i += blockDim.x) {
        int c = i / XS_W, j = i % XS_W;
        int tg = t0 - 31 + j;
        xs[i] = (tg >= 0 && tg < TTOT) ? x[(b * CC + c) * TTOT + tg] : 0.f;
    }
    for (int i = tid; i < NF_WS; i += blockDim.x) {
        int f = i / KK;
        float s1 = g1[f] * rsqrtf(v1[f] + EPSF);
        ws[i] = w1[i] * s1;
    }
    for (int i = tid; i < NF_AH; i += blockDim.x) ah[i] = ahat_g[i];
    for (int i = tid; i < NF_DW; i += blockDim.x) dw[i] = dww_g[i];
    if (tid < F1N) {
        float s1 = g1[tid] * rsqrtf(v1[tid] + EPSF);
        o1s[tid] = b1c[tid] * s1 + bb1[tid] - m1[tid] * s1;
        gw[tid]  = gcw[tid];
    }
    if (tid < C2N) {
        float s = g2[tid] * rsqrtf(v2[tid] + EPSF);
        s2[tid]  = s;
        sh2[tid] = bb2[tid] - m2[tid] * s;
    }
    __syncthreads();
    if (tid < C2N) {
        float wsum = 0.f;
        for (int c = 0; c < CC; ++c) wsum += dw[tid * CC + c];
        cst[tid] = gcb[tid >> 1] * wsum + dwb[tid];
    }
    __syncthreads();

    // thread -> (fq, tg, c): warp spans 32 consecutive c (conflict-free)
    const int fq = tid >> 7;         // 0..3  (filter quad)
    const int tg = (tid >> 6) & 1;   // 0..1  (t group)
    const int c  = tid & 63;
    const float* xrow = xs + c * XS_W;
    const float* wr0 = ws + (fq * 4 + 0) * KK;
    const float* wr1 = ws + (fq * 4 + 1) * KK;
    const float* wr2 = ws + (fq * 4 + 2) * KK;
    const float* wr3 = ws + (fq * 4 + 3) * KK;

    for (int chk = 0; chk < NCHUNK; ++chk) {
        const int ct = chk * TSUB;

        // ---- phase A: conv + BN1 + ELU -> es (one task/thread) ----
        {
            const int base = ct + tg * TGRP;
            float a0[TGRP], a1[TGRP], a2[TGRP], a3[TGRP], win[TGRP];
            #pragma unroll
            for (int i = 0; i < TGRP; ++i) {
                a0[i] = a1[i] = a2[i] = a3[i] = 0.f;
                win[i] = xrow[base + i];
            }
            int k = 0;
            for (int m = 0; m < 6; ++m) {
                #pragma unroll
                for (int kk = 0; kk < TGRP; ++kk) {
                    float w0 = wr0[k + kk], w1v = wr1[k + kk];
                    float w2v = wr2[k + kk], w3v = wr3[k + kk];
                    #pragma unroll
                    for (int i = 0; i < TGRP; ++i) {
                        float xv = win[(kk + i) % TGRP];
                        a0[i] = fmaf(w0, xv, a0[i]);
                        a1[i] = fmaf(w1v, xv, a1[i]);
                        a2[i] = fmaf(w2v, xv, a2[i]);
                        a3[i] = fmaf(w3v, xv, a3[i]);
                    }
                    win[kk] = xrow[base + k + kk + TGRP];
                }
                k += TGRP;
            }
            #pragma unroll
            for (int kk = 0; kk < 4; ++kk) {   // k = 60..63
                float w0 = wr0[60 + kk], w1v = wr1[60 + kk];
                float w2v = wr2[60 + kk], w3v = wr3[60 + kk];
                #pragma unroll
                for (int i = 0; i < TGRP; ++i) {
                    float xv = win[(kk + i) % TGRP];
                    a0[i] = fmaf(w0, xv, a0[i]);
                    a1[i] = fmaf(w1v, xv, a1[i]);
                    a2[i] = fmaf(w2v, xv, a2[i]);
                    a3[i] = fmaf(w3v, xv, a3[i]);
                }
                if (kk < 3) win[kk] = xrow[base + 60 + kk + TGRP];
            }
            const int f0 = fq * 4;
            float* e0 = es + ((f0 + 0) * CC + c) * ES_S + tg * TGRP;
            float* e1 = es + ((f0 + 1) * CC + c) * ES_S + tg * TGRP;
            float* e2 = es + ((f0 + 2) * CC + c) * ES_S + tg * TGRP;
            float* e3 = es + ((f0 + 3) * CC + c) * ES_S + tg * TGRP;
            float o0 = o1s[f0], o1 = o1s[f0 + 1], o2 = o1s[f0 + 2], o3 = o1s[f0 + 3];
            #pragma unroll
            for (int i = 0; i < TGRP; ++i) {
                e0[i] = eluf(a0[i] + o0);
                e1[i] = eluf(a1[i] + o1);
                e2[i] = eluf(a2[i] + o2);
                e3[i] = eluf(a3[i] + o3);
            }
        }
        __syncthreads();

        // ---- phase B: xg = mean_f es ----
        for (int idx = tid; idx < CC * TSUB; idx += blockDim.x) {
            int cc = idx / TSUB, tt = idx % TSUB;
            float s = 0.f;
            #pragma unroll
            for (int f = 0; f < F1N; ++f) s += es[(f * CC + cc) * ES_S + tt];
            xg[idx] = s * (1.f / F1N);
        }
        __syncthreads();

        // ---- phase C: ax = a_hat @ xg ----
        for (int idx = tid; idx < CC * TSUB; idx += blockDim.x) {
            int cc = idx / TSUB, tt = idx % TSUB;
            const float* ar = ah + cc * CC;
            float s = 0.f;
            #pragma unroll 8
            for (int j = 0; j < CC; ++j) s = fmaf(ar[j], xg[j * TSUB + tt], s);
            ax[idx] = s;
        }
        __syncthreads();

        // ---- phase D: depthwise expansion + GCN + BN2 -> g_h2 ----
        for (int idx = tid; idx < C2N * TSUB; idx += blockDim.x) {
            int c2 = idx / TSUB, tt = idx % TSUB;
            int f = c2 >> 1;
            float gwf = gw[f];
            const float* dr = dw + c2 * CC;
            float s = 0.f;
            #pragma unroll 8
            for (int cc = 0; cc < CC; ++cc)
                s = fmaf(dr[cc], es[(f * CC + cc) * ES_S + tt] + gwf * ax[cc * TSUB + tt], s);
            float outv = (s + cst[c2]) * s2[c2] + sh2[c2];
            g_h2[(b * C2N + c2) * TTOT + t0 + ct + tt] = outv;
        }
        __syncthreads();
    }
}

// ============================================================
// Kernel 2a: per-(b,c2) sum + max over t  -> g_stat
// grid (C2N, BB), 128 threads
// ============================================================
__global__ void __launch_bounds__(128, 8)
k2a_stats()
{
    __shared__ float ssum[4], smax[4];
    const int c2 = blockIdx.x, b = blockIdx.y;
    const int tid = threadIdx.x;
    const float* row = g_h2 + (b * C2N + c2) * TTOT;
    float s = 0.f, mx = -INFINITY;
    for (int t = tid; t < TTOT; t += 128) {
        float v = row[t];
        s += v; mx = fmaxf(mx, v);
    }
    #pragma unroll
    for (int o = 16; o > 0; o >>= 1) {
        s += __shfl_down_sync(0xffffffffu, s, o);
        mx = fmaxf(mx, __shfl_down_sync(0xffffffffu, mx, o));
    }
    if ((tid & 31) == 0) { ssum[tid >> 5] = s; smax[tid >> 5] = mx; }
    __syncthreads();
    if (tid == 0) {
        float ts = ssum[0] + ssum[1] + ssum[2] + ssum[3];
        float tm = fmaxf(fmaxf(ssum[0] * 0.f + smax[0], smax[1]), fmaxf(smax[2], smax[3]));
        g_stat[(b * C2N + c2) * 2 + 0] = ts;
        g_stat[(b * C2N + c2) * 2 + 1] = tm;
    }
}

// ============================================================
// Kernel 2b: channel attn + spatial attn + ELU + pool16 -> g_q
// grid (NTILE2, BB), 256 threads
// ============================================================
#define H2S_S 131   // padded stride (K2B_T + 2 halo -> 131 odd)
__global__ void __launch_bounds__(256, 4)
k2b_attpool(const float* __restrict__ caw1, const float* __restrict__ cab1,
            const float* __restrict__ caw2, const float* __restrict__ cab2,
            const float* __restrict__ saw,
            const float* __restrict__ sag, const float* __restrict__ sab,
            const float* __restrict__ sam, const float* __restrict__ sav)
{
    __shared__ float att[C2N];
    __shared__ float h2s[C2N * H2S_S];
    __shared__ float mms[K2B_T + 2], mxs[K2B_T + 2], sgs[K2B_T];
    __shared__ float sstat[C2N];

    const int tile = blockIdx.x, b = blockIdx.y;
    const int tid  = threadIdx.x;
    const int t0   = tile * K2B_T;
    const int tw   = (tile == NTILE2 - 1) ? (NPOOL * PWN - t0) : K2B_T; // 128 or 96
    const int nw   = tw / PWN;

    // channel attention (from precomputed stats)
    if (tid < C2N)
        sstat[tid] = g_stat[(b * C2N + tid) * 2] * (1.f / TTOT)
                   + g_stat[(b * C2N + tid) * 2 + 1];
    __syncthreads();
    if (tid < C2N) {
        float r0 = cab1[0], r1 = cab1[1];
        for (int j = 0; j < C2N; ++j) {
            r0 += caw1[j] * sstat[j];
            r1 += caw1[C2N + j] * sstat[j];
        }
        r0 = fmaxf(r0, 0.f); r1 = fmaxf(r1, 0.f);
        att[tid] = sigmf(cab2[tid] + caw2[tid * 2] * r0 + caw2[tid * 2 + 1] * r1);
    }
    __syncthreads();

    // load att-scaled h2 tile with +-1 halo
    const float* h2 = g_h2 + b * C2N * TTOT;
    for (int idx = tid; idx < C2N * (tw + 2); idx += 256) {
        int c2 = idx / (tw + 2), j = idx % (tw + 2);
        int t = t0 - 1 + j;
        float v = (t >= 0 && t < TTOT) ? h2[c2 * TTOT + t] * att[c2] : 0.f;
        h2s[c2 * H2S_S + j] = v;
    }
    __syncthreads();

    // spatial stats per t (incl. halo)
    for (int j = tid; j < tw + 2; j += 256) {
        float s = 0.f, mx = -INFINITY;
        #pragma unroll 8
        for (int c2 = 0; c2 < C2N; ++c2) {
            float v = h2s[c2 * H2S_S + j];
            s += v; mx = fmaxf(mx, v);
        }
        mms[j] = s * (1.f / C2N);
        mxs[j] = mx;
    }
    __syncthreads();

    // spatial attention: 1x3 conv (middle row of 3x3) + BN + sigmoid
    {
        float ssa = sag[0] * rsqrtf(sav[0] + EPSF);
        float sha = sab[0] - sam[0] * ssa;
        for (int j = tid; j < tw; j += 256) {
            int t = t0 + j;
            float acc = 0.f;
            #pragma unroll
            for (int kw = 0; kw < 3; ++kw) {
                int tt = t - 1 + kw;
                if (tt >= 0 && tt < TTOT)
                    acc += saw[3 + kw] * mms[j + kw] + saw[12 + kw] * mxs[j + kw];
            }
            sgs[j] = sigmf(acc * ssa + sha);
        }
    }
    __syncthreads();

    // ELU + avgpool16  (lane = c2 -> conflict-free h2s reads)
    {
        int c2 = tid & 31, w = tid >> 5;
        if (w < nw) {
            float acc = 0.f;
            #pragma unroll
            for (int j = 0; j < PWN; ++j) {
                int tl = w * PWN + j;
                acc += eluf(h2s[c2 * H2S_S + tl + 1] * sgs[tl]);
            }
            g_q[(b * C2N + c2) * NPOOL + tile * K2B_W + w] = acc * (1.f / PWN);
        }
    }
}

// ============================================================
// Kernel 2c: depthwise sep conv + BN3 + ELU + pool16 -> out
// grid (BB), 128 threads
// ============================================================
__global__ void __launch_bounds__(128, 8)
k2c_tail(const float* __restrict__ sepw, const float* __restrict__ sepb,
         const float* __restrict__ g3, const float* __restrict__ bb3,
         const float* __restrict__ m3, const float* __restrict__ v3,
         float* __restrict__ out)
{
    __shared__ float qs[C2N * NPOOL];
    const int b = blockIdx.x, tid = threadIdx.x;
    for (int i = tid; i < C2N * NPOOL; i += 128)
        qs[i] = g_q[b * C2N * NPOOL + i];
    __syncthreads();
    if (tid < C2N * 3) {
        int c2 = tid / 3, to = tid % 3;
        float s3  = g3[c2] * rsqrtf(v3[c2] + EPSF);
        float sh3 = bb3[c2] - m3[c2] * s3;
        float acc = 0.f;
        for (int j = 0; j < PWN; ++j) {
            int t = to * PWN + j;
            float y = sepb[c2];
            #pragma unroll
            for (int u = 0; u < PWN; ++u) {
                int tq = t - 7 + u;
                if (tq >= 0 && tq < NPOOL) y += sepw[c2 * PWN + u] * qs[c2 * NPOOL + tq];
            }
            acc += eluf(y * s3 + sh3);
        }
        out[b * (C2N * 3) + tid] = acc * (1.f / PWN);
    }
}

// ============================================================
extern "C" void kernel_launch(void* const* d_in, const int* in_sizes, int n_in,
                              void* d_out, int out_size)
{
    const float* x     = (const float*)d_in[0];
    const float* ahat  = (const float*)d_in[1];
    const float* w1    = (const float*)d_in[2];
    const float* b1c   = (const float*)d_in[3];
    const float* g1    = (const float*)d_in[4];
    const float* bb1   = (const float*)d_in[5];
    const float* m1    = (const float*)d_in[6];
    const float* v1    = (const float*)d_in[7];
    const float* gcw   = (const float*)d_in[8];
    const float* gcb   = (const float*)d_in[9];
    const float* dww   = (const float*)d_in[10];
    const float* dwb   = (const float*)d_in[11];
    const float* g2    = (const float*)d_in[12];
    const float* bb2   = (const float*)d_in[13];
    const float* m2    = (const float*)d_in[14];
    const float* v2    = (const float*)d_in[15];
    const float* caw1  = (const float*)d_in[16];
    const float* cab1  = (const float*)d_in[17];
    const float* caw2  = (const float*)d_in[18];
    const float* cab2  = (const float*)d_in[19];
    const float* saw   = (const float*)d_in[20];
    const float* sag   = (const float*)d_in[21];
    const float* sab   = (const float*)d_in[22];
    const float* sam   = (const float*)d_in[23];
    const float* sav   = (const float*)d_in[24];
    const float* sepw  = (const float*)d_in[25];
    const float* sepb  = (const float*)d_in[26];
    const float* g3    = (const float*)d_in[27];
    const float* bb3   = (const float*)d_in[28];
    const float* m3    = (const float*)d_in[29];
    const float* v3    = (const float*)d_in[30];

    cudaFuncSetAttribute(k1_front, cudaFuncAttributeMaxDynamicSharedMemorySize,
                         SMEM_BYTES);

    dim3 grid1(NTILE, BB);
    k1_front<<<grid1, 512, SMEM_BYTES>>>(x, ahat, w1, b1c, g1, bb1, m1, v1,
                                         gcw, gcb, dww, dwb, g2, bb2, m2, v2);

    dim3 grid2a(C2N, BB);
    k2a_stats<<<grid2a, 128>>>();

    dim3 grid2b(NTILE2, BB);
    k2b_attpool<<<grid2b, 256>>>(caw1, cab1, caw2, cab2, saw, sag, sab, sam, sav);

    k2c_tail<<<BB, 128>>>(sepw, sepb, g3, bb3, m3, v3, (float*)d_out);
}